// round 16
// baseline (speedup 1.0000x reference)
#include <cuda_runtime.h>
#include <cuda_bf16.h>
#include <math.h>
#include <stdint.h>

// Model dims
#define QL 512
#define BS 8
#define VC 32000
#define DM 1024
#define NH 16
#define DHD 64
#define FFD 4096
#define NL 4
#define RL 513
#define TOK 4096
#define BH 128
#define ATT_SCALE 0.125f

// ---------------------------------------------------------------------------
// Scratch
// ---------------------------------------------------------------------------
__device__ float g_core[TOK * DM];
__device__ float g_big[TOK * FFD];          // QKV output (fp32, read by attention)
__device__ float g_tmp[TOK * DM];
__device__ float g_h[TOK * DM];
__device__ float g_r[RL * DM];
__device__ float g_rqkv[RL * 3 * DM];
__device__ float g_qr[(size_t)BH * QL * RL];
// bf16 split buffers
__device__ __nv_bfloat16 g_ah[TOK * FFD];        // FFN1 output split hi
__device__ __nv_bfloat16 g_al[TOK * FFD];        // FFN1 output split lo
__device__ __nv_bfloat16 g_wh[DM * FFD];         // weight split
__device__ __nv_bfloat16 g_wl[DM * FFD];
__device__ __nv_bfloat16 g_eh[(size_t)VC * DM];  // embedding split
__device__ __nv_bfloat16 g_el[(size_t)VC * DM];
__device__ __nv_bfloat16 g_rh[RL * DM];
__device__ __nv_bfloat16 g_rl[RL * DM];
__device__ __nv_bfloat16 g_ch[TOK * DM];         // core split (feeds QKV / logits)
__device__ __nv_bfloat16 g_cl[TOK * DM];
__device__ __nv_bfloat16 g_vh[TOK * DM];         // attn-vec split (feeds Wo)
__device__ __nv_bfloat16 g_vl[TOK * DM];
__device__ __nv_bfloat16 g_hsh[TOK * DM];        // h split (feeds FFN1)
__device__ __nv_bfloat16 g_hsl[TOK * DM];

static __device__ __forceinline__ uint32_t s2u(const void* p) {
    return (uint32_t)__cvta_generic_to_shared(p);
}

#define LDSM4(R, addr)                                                           \
    asm volatile("ldmatrix.sync.aligned.m8n8.x4.shared.b16 {%0,%1,%2,%3}, [%4];" \
                 : "=r"(R[0]), "=r"(R[1]), "=r"(R[2]), "=r"(R[3]) : "r"(addr));
#define LDSM4T(R, addr)                                                                \
    asm volatile("ldmatrix.sync.aligned.m8n8.x4.trans.shared.b16 {%0,%1,%2,%3}, [%4];" \
                 : "=r"(R[0]), "=r"(R[1]), "=r"(R[2]), "=r"(R[3]) : "r"(addr));
#define MMA_BF16(ac, A, b0, b1)                                                  \
    asm volatile("mma.sync.aligned.m16n8k16.row.col.f32.bf16.bf16.f32 "          \
                 "{%0,%1,%2,%3}, {%4,%5,%6,%7}, {%8,%9}, {%0,%1,%2,%3};"         \
                 : "+f"(ac[0]), "+f"(ac[1]), "+f"(ac[2]), "+f"(ac[3])            \
                 : "r"(A[0]), "r"(A[1]), "r"(A[2]), "r"(A[3]), "r"(b0), "r"(b1));

static __device__ __forceinline__ void cp16(__nv_bfloat16* dst,
                                            const __nv_bfloat16* src, bool pred) {
    uint32_t d = s2u(dst);
    int n = pred ? 16 : 0;
    asm volatile("cp.async.cg.shared.global [%0], [%1], 16, %2;" ::"r"(d), "l"(src), "r"(n));
}

static __device__ __forceinline__ void split1(float v, __nv_bfloat16& hi, __nv_bfloat16& lo) {
    hi = __float2bfloat16(v);
    lo = __float2bfloat16(v - __bfloat162float(hi));
}

static __device__ __forceinline__ void split_store4(float x0, float x1, float x2, float x3,
                                                    __nv_bfloat16* H, __nv_bfloat16* L) {
    __nv_bfloat16 h0, h1, h2, h3, l0, l1, l2, l3;
    split1(x0, h0, l0); split1(x1, h1, l1);
    split1(x2, h2, l2); split1(x3, h3, l3);
    *(__nv_bfloat162*)(H)     = __nv_bfloat162(h0, h1);
    *(__nv_bfloat162*)(H + 2) = __nv_bfloat162(h2, h3);
    *(__nv_bfloat162*)(L)     = __nv_bfloat162(l0, l1);
    *(__nv_bfloat162*)(L + 2) = __nv_bfloat162(l2, l3);
}

// ---------------------------------------------------------------------------
// Split fp32 -> (hi, lo) bf16
// ---------------------------------------------------------------------------
__global__ void k_split(const float* __restrict__ x, __nv_bfloat16* __restrict__ h,
                        __nv_bfloat16* __restrict__ l, int n) {
    int i = (blockIdx.x * 256 + threadIdx.x) * 4;
    if (i >= n) return;
    float4 v = *(const float4*)(x + i);
    split_store4(v.x, v.y, v.z, v.w, h + i, l + i);
}

// ---------------------------------------------------------------------------
// Split-bf16 tensor-core GEMM, 2-stage cp.async pipeline.
// Single __syncthreads per k-iter: wait(0) -> sync -> issue next -> compute.
// (Issuing loads(kt+1) after the sync guarantees all threads finished reading
//  buffer (kt+1)&1 in iteration kt-1, so the trailing sync is unnecessary.)
// ---------------------------------------------------------------------------
template <int ACT, bool TB, bool SPLIT_OUT>
__global__ __launch_bounds__(256, 2)
void k_mgemm(const __nv_bfloat16* __restrict__ Ah, const __nv_bfloat16* __restrict__ Al,
             const __nv_bfloat16* __restrict__ Bh, const __nv_bfloat16* __restrict__ Bl,
             const float* __restrict__ bias, float* __restrict__ C,
             __nv_bfloat16* __restrict__ Oh, __nv_bfloat16* __restrict__ Ol,
             int M, int N, int K) {
    constexpr int BSTR = TB ? 40 : 136;
    constexpr int ASTG = 128 * 40;
    constexpr int BSTG = TB ? 128 * 40 : 32 * 136;
    constexpr int STG = 2 * ASTG + 2 * BSTG;
    extern __shared__ __nv_bfloat16 smem[];

    int tid = threadIdx.x;
    int m0 = blockIdx.y << 7, n0 = blockIdx.x << 7;
    int lane = tid & 31, warp = tid >> 5;
    int wm = warp >> 1, wn = warp & 1;

    float acc[2][8][4];
#pragma unroll
    for (int a = 0; a < 2; a++)
#pragma unroll
        for (int b = 0; b < 8; b++)
#pragma unroll
            for (int c = 0; c < 4; c++) acc[a][b][c] = 0.f;

    auto load_stage = [&](int k0, int s) {
        __nv_bfloat16* sAh = smem + s * STG;
        __nv_bfloat16* sAl = sAh + ASTG;
        __nv_bfloat16* sBh = sAl + ASTG;
        __nv_bfloat16* sBl = sBh + BSTG;
#pragma unroll
        for (int u = 0; u < 2; u++) {
            int p = tid + u * 256;
            int row = p >> 2, kq = (p & 3) << 3;
            bool ok = (m0 + row) < M;
            size_t off = (size_t)(m0 + row) * K + k0 + kq;
            cp16(&sAh[row * 40 + kq], Ah + off, ok);
            cp16(&sAl[row * 40 + kq], Al + off, ok);
        }
#pragma unroll
        for (int u = 0; u < 2; u++) {
            int p = tid + u * 256;
            if (TB) {
                int row = p >> 2, kq = (p & 3) << 3;
                size_t off = (size_t)(n0 + row) * K + k0 + kq;
                cp16(&sBh[row * 40 + kq], Bh + off, true);
                cp16(&sBl[row * 40 + kq], Bl + off, true);
            } else {
                int row = p >> 4, nq = (p & 15) << 3;
                size_t off = (size_t)(k0 + row) * N + n0 + nq;
                cp16(&sBh[row * 136 + nq], Bh + off, true);
                cp16(&sBl[row * 136 + nq], Bl + off, true);
            }
        }
        asm volatile("cp.async.commit_group;");
    };

    int KT = K >> 5;
    load_stage(0, 0);

    for (int kt = 0; kt < KT; kt++) {
        asm volatile("cp.async.wait_group 0;");
        __syncthreads();
        if (kt + 1 < KT) load_stage((kt + 1) << 5, (kt + 1) & 1);

        const __nv_bfloat16* sAh = smem + (kt & 1) * STG;
        const __nv_bfloat16* sAl = sAh + ASTG;
        const __nv_bfloat16* sBh = sAl + ASTG;
        const __nv_bfloat16* sBl = sBh + BSTG;

#pragma unroll
        for (int ks = 0; ks < 32; ks += 16) {
            uint32_t ah[2][4], al[2][4];
#pragma unroll
            for (int mt = 0; mt < 2; mt++) {
                int rb = wm * 32 + mt * 16 + (lane & 15);
                int kc = ks + ((lane >> 4) << 3);
                LDSM4(ah[mt], s2u(&sAh[rb * 40 + kc]));
                LDSM4(al[mt], s2u(&sAl[rb * 40 + kc]));
            }
#pragma unroll
            for (int np = 0; np < 4; np++) {
                int nb = wn * 64 + np * 16;
                uint32_t bh[4], bl[4];
                int g = lane >> 3, l8 = lane & 7;
                if (TB) {
                    int nr = nb + ((g >> 1) << 3) + l8;
                    int kc = ks + ((g & 1) << 3);
                    LDSM4(bh, s2u(&sBh[nr * BSTR + kc]));
                    LDSM4(bl, s2u(&sBl[nr * BSTR + kc]));
                } else {
                    int kr = ks + ((g & 1) << 3) + l8;
                    int nc = nb + ((g >> 1) << 3);
                    LDSM4T(bh, s2u(&sBh[kr * BSTR + nc]));
                    LDSM4T(bl, s2u(&sBl[kr * BSTR + nc]));
                }
#pragma unroll
                for (int mt = 0; mt < 2; mt++) {
#pragma unroll
                    for (int j = 0; j < 2; j++) {
                        float* ac = acc[mt][np * 2 + j];
                        MMA_BF16(ac, ah[mt], bh[2 * j], bh[2 * j + 1]);
                        MMA_BF16(ac, ah[mt], bl[2 * j], bl[2 * j + 1]);
                        MMA_BF16(ac, al[mt], bh[2 * j], bh[2 * j + 1]);
                    }
                }
            }
        }
    }

#pragma unroll
    for (int mt = 0; mt < 2; mt++) {
#pragma unroll
        for (int np = 0; np < 4; np++) {
#pragma unroll
            for (int j = 0; j < 2; j++) {
                int nt = np * 2 + j;
                int col = n0 + wn * 64 + np * 16 + j * 8 + (lane & 3) * 2;
                int rb = m0 + wm * 32 + mt * 16 + (lane >> 2);
#pragma unroll
                for (int hh = 0; hh < 2; hh++) {
                    int r = rb + hh * 8;
                    if (r >= M) continue;
                    float v0 = acc[mt][nt][hh * 2];
                    float v1 = acc[mt][nt][hh * 2 + 1];
                    if (bias) { v0 += bias[col]; v1 += bias[col + 1]; }
                    if (ACT == 1) {
                        v0 = 0.5f * v0 * (1.f + erff(v0 * 0.70710678118654752f));
                        v1 = 0.5f * v1 * (1.f + erff(v1 * 0.70710678118654752f));
                    }
                    if (SPLIT_OUT) {
                        __nv_bfloat16 h0, h1, l0, l1;
                        split1(v0, h0, l0);
                        split1(v1, h1, l1);
                        *(__nv_bfloat162*)(Oh + (size_t)r * N + col) = __nv_bfloat162(h0, h1);
                        *(__nv_bfloat162*)(Ol + (size_t)r * N + col) = __nv_bfloat162(l0, l1);
                    } else {
                        *(float2*)(C + (size_t)r * N + col) = make_float2(v0, v1);
                    }
                }
            }
        }
    }
}

// ---------------------------------------------------------------------------
// Embedding lookup * sqrt(D) + fused core split
// ---------------------------------------------------------------------------
__global__ void k_embed(const int* __restrict__ src, const float* __restrict__ emb) {
    int t = blockIdx.x;
    int tok = src[t];
    const float4* e = (const float4*)(emb + (size_t)tok * DM);
    size_t base = (size_t)t * DM;
    for (int d = threadIdx.x; d < DM / 4; d += blockDim.x) {
        float4 v = e[d];
        v.x *= 32.f; v.y *= 32.f; v.z *= 32.f; v.w *= 32.f;
        *(float4*)(g_core + base + d * 4) = v;
        split_store4(v.x, v.y, v.z, v.w, g_ch + base + d * 4, g_cl + base + d * 4);
    }
}

__global__ void k_posemb() {
    int p = blockIdx.x;
    double pos = (double)(QL - p);
    for (int d = threadIdx.x; d < DM; d += blockDim.x) {
        int j = d & 511;
        double inv = exp(-((double)(2 * j) / (double)DM) * log(10000.0));
        double a = pos * inv;
        g_r[p * DM + d] = (d < 512) ? (float)sin(a) : (float)cos(a);
    }
}

// ---------------------------------------------------------------------------
// fp32 64x64 NT tile MMA (proven attention compute primitive)
// ---------------------------------------------------------------------------
__device__ __forceinline__ void mma_nt64(const float (*X)[68], const float (*Y)[68],
                                         int ty, int tx, float acc[4][4]) {
#pragma unroll
    for (int d4 = 0; d4 < 16; d4++) {
        float4 xv[4], yv[4];
#pragma unroll
        for (int ii = 0; ii < 4; ii++) xv[ii] = *(const float4*)&X[ty * 4 + ii][d4 * 4];
#pragma unroll
        for (int jj = 0; jj < 4; jj++) yv[jj] = *(const float4*)&Y[tx * 4 + jj][d4 * 4];
#pragma unroll
        for (int ii = 0; ii < 4; ii++)
#pragma unroll
            for (int jj = 0; jj < 4; jj++)
                acc[ii][jj] += xv[ii].x * yv[jj].x + xv[ii].y * yv[jj].y +
                               xv[ii].z * yv[jj].z + xv[ii].w * yv[jj].w;
    }
}

// ---------------------------------------------------------------------------
// k_qr: qr[bn,i,jr] = q_bias . rk (unchanged)
// ---------------------------------------------------------------------------
__global__ __launch_bounds__(256) void k_qr() {
    int bn = blockIdx.z, b = bn >> 4, n = bn & 15;
    int i0 = blockIdx.y << 6, jr0 = blockIdx.x << 6;
    if (jr0 + i0 + 126 < QL) return;
    __shared__ float Qs[64][68], Rs[64][68];
    int tid = threadIdx.x;
    const float* rql = g_rqkv + (size_t)QL * 3 * DM + n * DHD;
#pragma unroll
    for (int u = 0; u < 16; u++) {
        int idx = tid + u * 256;
        int rr = idx >> 6, d = idx & 63;
        Qs[rr][d] = g_big[((size_t)(i0 + rr) * BS + b) * (3 * DM) + n * DHD + d] + rql[d];
        int jr = jr0 + rr;
        Rs[rr][d] = (jr < RL) ? g_rqkv[(size_t)jr * (3 * DM) + DM + n * DHD + d] : 0.f;
    }
    __syncthreads();
    int ty = tid >> 4, tx = tid & 15;
    float acc[4][4] = {};
    mma_nt64(Qs, Rs, ty, tx, acc);
    float* out = g_qr + (size_t)bn * QL * RL;
#pragma unroll
    for (int ii = 0; ii < 4; ii++) {
        int i = i0 + ty * 4 + ii;
#pragma unroll
        for (int jj = 0; jj < 4; jj++) {
            int jr = jr0 + tx * 4 + jj;
            if (jr < RL) out[(size_t)i * RL + jr] = acc[ii][jj];
        }
    }
}

// ---------------------------------------------------------------------------
// Fused flash attention (champion-identical)
// ---------------------------------------------------------------------------
__global__ __launch_bounds__(256) void k_flash() {
    int bn = blockIdx.y, b = bn >> 4, n = bn & 15;
    int it = blockIdx.x;
    int i0 = it << 6;
    extern __shared__ float fsm[];
    float (*Qs)[68] = (float(*)[68])fsm;
    float (*Ks)[68] = (float(*)[68])(fsm + 64 * 68);
    float (*Vs)[68] = (float(*)[68])(fsm + 2 * 64 * 68);
    float (*Ps)[68] = (float(*)[68])(fsm + 3 * 64 * 68);
    int tid = threadIdx.x, ty = tid >> 4, tx = tid & 15;

    const float* rql = g_rqkv + (size_t)QL * 3 * DM + n * DHD;
#pragma unroll
    for (int u = 0; u < 16; u++) {
        int idx = tid + u * 256;
        int rr = idx >> 6, d = idx & 63;
        Qs[rr][d] = g_big[((size_t)(i0 + rr) * BS + b) * (3 * DM) + n * DHD + d] + rql[d];
    }

    float o[4][4];
    float m[4], l[4];
#pragma unroll
    for (int ii = 0; ii < 4; ii++) {
        m[ii] = -INFINITY;
        l[ii] = 0.f;
#pragma unroll
        for (int jj = 0; jj < 4; jj++) o[ii][jj] = 0.f;
    }

    const float* qrb = g_qr + (size_t)bn * QL * RL;

    for (int jt = 0; jt <= it; jt++) {
        int j0 = jt << 6;
        __syncthreads();
#pragma unroll
        for (int u = 0; u < 16; u++) {
            int idx = tid + u * 256;
            int rr = idx >> 6, d = idx & 63;
            Ks[rr][d] = g_big[((size_t)(j0 + rr) * BS + b) * (3 * DM) + DM + n * DHD + d];
            Vs[rr][d] = g_big[((size_t)(j0 + rr) * BS + b) * (3 * DM) + 2 * DM + n * DHD + d];
        }
        __syncthreads();

        float acc[4][4] = {};
        mma_nt64(Qs, Ks, ty, tx, acc);

#pragma unroll
        for (int ii = 0; ii < 4; ii++) {
            int i = i0 + ty * 4 + ii;
            float s[4];
#pragma unroll
            for (int jj = 0; jj < 4; jj++) {
                int j = j0 + tx * 4 + jj;
                s[jj] = (j > i) ? -INFINITY
                                : (acc[ii][jj] + qrb[(size_t)i * RL + (QL + j - i)]) * ATT_SCALE;
            }
            float mx = fmaxf(fmaxf(s[0], s[1]), fmaxf(s[2], s[3]));
#pragma unroll
            for (int off = 8; off >= 1; off >>= 1)
                mx = fmaxf(mx, __shfl_xor_sync(0xffffffffu, mx, off));
            float newm = fmaxf(m[ii], mx);
            float corr = expf(m[ii] - newm);
            float p[4];
            float ps = 0.f;
#pragma unroll
            for (int jj = 0; jj < 4; jj++) {
                p[jj] = expf(s[jj] - newm);
                ps += p[jj];
            }
#pragma unroll
            for (int off = 8; off >= 1; off >>= 1)
                ps += __shfl_xor_sync(0xffffffffu, ps, off);
            l[ii] = l[ii] * corr + ps;
            m[ii] = newm;
#pragma unroll
            for (int jj = 0; jj < 4; jj++) o[ii][jj] *= corr;
            *(float4*)&Ps[ty * 4 + ii][tx * 4] = make_float4(p[0], p[1], p[2], p[3]);
        }
        __syncthreads();

#pragma unroll
        for (int k4 = 0; k4 < 16; k4++) {
            float4 pr[4];
#pragma unroll
            for (int ii = 0; ii < 4; ii++) pr[ii] = *(const float4*)&Ps[ty * 4 + ii][k4 * 4];
#pragma unroll
            for (int kk = 0; kk < 4; kk++) {
                float4 vv = *(const float4*)&Vs[k4 * 4 + kk][tx * 4];
#pragma unroll
                for (int ii = 0; ii < 4; ii++) {
                    float pv = ((const float*)&pr[ii])[kk];
                    o[ii][0] += pv * vv.x;
                    o[ii][1] += pv * vv.y;
                    o[ii][2] += pv * vv.z;
                    o[ii][3] += pv * vv.w;
                }
            }
        }
    }

#pragma unroll
    for (int ii = 0; ii < 4; ii++) {
        float invl = 1.f / l[ii];
        int i = i0 + ty * 4 + ii;
        size_t off = ((size_t)i * BS + b) * DM + n * DHD + tx * 4;
        split_store4(o[ii][0] * invl, o[ii][1] * invl, o[ii][2] * invl, o[ii][3] * invl,
                     g_vh + off, g_vl + off);
    }
}

// ---------------------------------------------------------------------------
// O = LayerNorm(A + B) * gamma + beta; optional fused split outputs
// ---------------------------------------------------------------------------
__global__ __launch_bounds__(256) void k_lnres(const float* __restrict__ A,
                                               const float* __restrict__ Bi,
                                               const float* __restrict__ G,
                                               const float* __restrict__ Be,
                                               float* __restrict__ O,
                                               __nv_bfloat16* __restrict__ Oh,
                                               __nv_bfloat16* __restrict__ Ol) {
    int row = blockIdx.x, tid = threadIdx.x;
    size_t base = (size_t)row * DM + tid * 4;
    float4 va = *(const float4*)(A + base);
    float4 vb = *(const float4*)(Bi + base);
    float x[4] = {va.x + vb.x, va.y + vb.y, va.z + vb.z, va.w + vb.w};
    float s = x[0] + x[1] + x[2] + x[3];
    float s2 = x[0] * x[0] + x[1] * x[1] + x[2] * x[2] + x[3] * x[3];
    __shared__ float rs[256], rs2[256];
    rs[tid] = s;
    rs2[tid] = s2;
    __syncthreads();
    for (int st = 128; st > 0; st >>= 1) {
        if (tid < st) { rs[tid] += rs[tid + st]; rs2[tid] += rs2[tid + st]; }
        __syncthreads();
    }
    float mean = rs[0] * (1.f / (float)DM);
    float var = rs2[0] * (1.f / (float)DM) - mean * mean;
    float inv = rsqrtf(var + 1e-5f);
    float4 g4 = *(const float4*)(G + tid * 4);
    float4 b4 = *(const float4*)(Be + tid * 4);
    float y[4];
    y[0] = (x[0] - mean) * inv * g4.x + b4.x;
    y[1] = (x[1] - mean) * inv * g4.y + b4.y;
    y[2] = (x[2] - mean) * inv * g4.z + b4.z;
    y[3] = (x[3] - mean) * inv * g4.w + b4.w;
    *(float4*)(O + base) = make_float4(y[0], y[1], y[2], y[3]);
    if (Oh) split_store4(y[0], y[1], y[2], y[3], Oh + base, Ol + base);
}

// ---------------------------------------------------------------------------
// Fused double-LN: src2 = LN(core+att); h = LN(core+src2)
// ---------------------------------------------------------------------------
__global__ __launch_bounds__(256) void k_lnres2(const float* __restrict__ core,
                                                const float* __restrict__ att,
                                                const float* __restrict__ G0,
                                                const float* __restrict__ B0,
                                                const float* __restrict__ G1,
                                                const float* __restrict__ B1,
                                                float* __restrict__ H,
                                                __nv_bfloat16* __restrict__ Hh,
                                                __nv_bfloat16* __restrict__ Hl) {
    int row = blockIdx.x, tid = threadIdx.x;
    size_t base = (size_t)row * DM + tid * 4;
    float4 vc = *(const float4*)(core + base);
    float4 va = *(const float4*)(att + base);
    float c[4] = {vc.x, vc.y, vc.z, vc.w};
    float x[4] = {vc.x + va.x, vc.y + va.y, vc.z + va.z, vc.w + va.w};
    __shared__ float rs[256], rs2[256];
    float s = x[0] + x[1] + x[2] + x[3];
    float s2 = x[0] * x[0] + x[1] * x[1] + x[2] * x[2] + x[3] * x[3];
    rs[tid] = s; rs2[tid] = s2;
    __syncthreads();
    for (int st = 128; st > 0; st >>= 1) {
        if (tid < st) { rs[tid] += rs[tid + st]; rs2[tid] += rs2[tid + st]; }
        __syncthreads();
    }
    float mean = rs[0] * (1.f / (float)DM);
    float var = rs2[0] * (1.f / (float)DM) - mean * mean;
    float inv = rsqrtf(var + 1e-5f);
    float4 g0 = *(const float4*)(G0 + tid * 4);
    float4 b0 = *(const float4*)(B0 + tid * 4);
    float y[4];   // core + src2
    y[0] = c[0] + (x[0] - mean) * inv * g0.x + b0.x;
    y[1] = c[1] + (x[1] - mean) * inv * g0.y + b0.y;
    y[2] = c[2] + (x[2] - mean) * inv * g0.z + b0.z;
    y[3] = c[3] + (x[3] - mean) * inv * g0.w + b0.w;
    __syncthreads();
    s = y[0] + y[1] + y[2] + y[3];
    s2 = y[0] * y[0] + y[1] * y[1] + y[2] * y[2] + y[3] * y[3];
    rs[tid] = s; rs2[tid] = s2;
    __syncthreads();
    for (int st = 128; st > 0; st >>= 1) {
        if (tid < st) { rs[tid] += rs[tid + st]; rs2[tid] += rs2[tid + st]; }
        __syncthreads();
    }
    mean = rs[0] * (1.f / (float)DM);
    var = rs2[0] * (1.f / (float)DM) - mean * mean;
    inv = rsqrtf(var + 1e-5f);
    float4 g1 = *(const float4*)(G1 + tid * 4);
    float4 b1 = *(const float4*)(B1 + tid * 4);
    float h[4];
    h[0] = (y[0] - mean) * inv * g1.x + b1.x;
    h[1] = (y[1] - mean) * inv * g1.y + b1.y;
    h[2] = (y[2] - mean) * inv * g1.z + b1.z;
    h[3] = (y[3] - mean) * inv * g1.w + b1.w;
    *(float4*)(H + base) = make_float4(h[0], h[1], h[2], h[3]);
    split_store4(h[0], h[1], h[2], h[3], Hh + base, Hl + base);
}

// ---------------------------------------------------------------------------
// Launch sequence. Prologue reordered so the ncu-captured launch slot lands
// on the QKV k_mgemm (observability; dependencies preserved).
// ---------------------------------------------------------------------------
extern "C" void kernel_launch(void* const* d_in, const int* in_sizes, int n_in,
                              void* d_out, int out_size) {
    const int*   src   = (const int*)d_in[0];
    const float* emb   = (const float*)d_in[1];
    const float* dec_b = (const float*)d_in[2];
    const float* Wqkv  = (const float*)d_in[3];
    const float* Wo    = (const float*)d_in[4];
    const float* ln0_g = (const float*)d_in[5];
    const float* ln0_b = (const float*)d_in[6];
    const float* W1    = (const float*)d_in[7];
    const float* b1    = (const float*)d_in[8];
    const float* W2    = (const float*)d_in[9];
    const float* b2    = (const float*)d_in[10];
    const float* ln1_g = (const float*)d_in[11];
    const float* ln1_b = (const float*)d_in[12];
    const float* ln2_g = (const float*)d_in[13];
    const float* ln2_b = (const float*)d_in[14];
    float* out = (float*)d_out;

    float *core, *big, *tmp, *h, *r, *rqkv;
    cudaGetSymbolAddress((void**)&core, g_core);
    cudaGetSymbolAddress((void**)&big,  g_big);
    cudaGetSymbolAddress((void**)&tmp,  g_tmp);
    cudaGetSymbolAddress((void**)&h,    g_h);
    cudaGetSymbolAddress((void**)&r,    g_r);
    cudaGetSymbolAddress((void**)&rqkv, g_rqkv);
    __nv_bfloat16 *ah, *al, *wh, *wl, *eh, *el, *rh, *rl, *ch, *cl, *vh, *vl, *hsh, *hsl;
    cudaGetSymbolAddress((void**)&ah,  g_ah);
    cudaGetSymbolAddress((void**)&al,  g_al);
    cudaGetSymbolAddress((void**)&wh,  g_wh);
    cudaGetSymbolAddress((void**)&wl,  g_wl);
    cudaGetSymbolAddress((void**)&eh,  g_eh);
    cudaGetSymbolAddress((void**)&el,  g_el);
    cudaGetSymbolAddress((void**)&rh,  g_rh);
    cudaGetSymbolAddress((void**)&rl,  g_rl);
    cudaGetSymbolAddress((void**)&ch,  g_ch);
    cudaGetSymbolAddress((void**)&cl,  g_cl);
    cudaGetSymbolAddress((void**)&vh,  g_vh);
    cudaGetSymbolAddress((void**)&vl,  g_vl);
    cudaGetSymbolAddress((void**)&hsh, g_hsh);
    cudaGetSymbolAddress((void**)&hsl, g_hsl);

    const int SMEM_NN = 75776, SMEM_NT = 81920;
    const int SMEM_FLASH = 4 * 64 * 68 * 4;   // 69632
    cudaFuncSetAttribute(k_mgemm<0, false, false>,
                         cudaFuncAttributeMaxDynamicSharedMemorySize, SMEM_NN);
    cudaFuncSetAttribute(k_mgemm<1, false, true>,
                         cudaFuncAttributeMaxDynamicSharedMemorySize, SMEM_NN);
    cudaFuncSetAttribute(k_mgemm<0, true, false>,
                         cudaFuncAttributeMaxDynamicSharedMemorySize, SMEM_NT);
    cudaFuncSetAttribute(k_flash,
                         cudaFuncAttributeMaxDynamicSharedMemorySize, SMEM_FLASH);

    auto split = [](const float* x, __nv_bfloat16* hh, __nv_bfloat16* ll, size_t n) {
        k_split<<<(unsigned)((n + 1023) / 1024), 256>>>(x, hh, ll, (int)n);
    };

    // Prologue — QKV GEMM of layer 0 hoisted to launch #4 (ncu capture slot).
    k_embed<<<TOK, 256>>>(src, emb);                 // #1: core fp32 + (ch, cl)
    k_posemb<<<RL, 256>>>();                         // #2
    split(Wqkv, wh, wl, (size_t)DM * 3 * DM);        // #3: layer-0 weight split
    k_mgemm<0, false, false><<<dim3(3 * DM / 128, TOK / 128), 256, SMEM_NN>>>(
        ch, cl, wh, wl, nullptr, big, nullptr, nullptr, TOK, 3 * DM, DM);  // #4
    split(emb, eh, el, (size_t)VC * DM);
    split(r, rh, rl, (size_t)RL * DM);

    for (int l = 0; l < NL; l++) {
        const float* Wq = Wqkv + (size_t)l * DM * 3 * DM;
        if (l > 0) {
            split(Wq, wh, wl, (size_t)DM * 3 * DM);
            // qkv = core @ Wqkv[l]
            k_mgemm<0, false, false><<<dim3(3 * DM / 128, TOK / 128), 256, SMEM_NN>>>(
                ch, cl, wh, wl, nullptr, big, nullptr, nullptr, TOK, 3 * DM, DM);
        }
        // rqkv = r @ Wqkv[l]  (wh/wl still hold Wq[l])
        k_mgemm<0, false, false><<<dim3(3 * DM / 128, (RL + 127) / 128), 256, SMEM_NN>>>(
            rh, rl, wh, wl, nullptr, rqkv, nullptr, nullptr, RL, 3 * DM, DM);
        // attention: qr, then fused score+softmax+PV
        k_qr<<<dim3(9, 8, BH), 256>>>();
        k_flash<<<dim3(8, BH), 256, SMEM_FLASH>>>();   // -> (vh, vl)
        // attn_out = vec @ Wo[l]
        split(Wo + (size_t)l * DM * DM, wh, wl, (size_t)DM * DM);
        k_mgemm<0, false, false><<<dim3(DM / 128, TOK / 128), 256, SMEM_NN>>>(
            vh, vl, wh, wl, nullptr, tmp, nullptr, nullptr, TOK, DM, DM);
        // fused: src2 = LN(core+att); h = LN(core+src2) (+ split for FFN1)
        k_lnres2<<<TOK, 256>>>(core, tmp, ln0_g + l * DM, ln0_b + l * DM,
                               ln1_g + l * DM, ln1_b + l * DM, h, hsh, hsl);
        // ffn hidden = gelu(h @ W1 + b1) -> split bf16 directly
        split(W1 + (size_t)l * DM * FFD, wh, wl, (size_t)DM * FFD);
        k_mgemm<1, false, true><<<dim3(FFD / 128, TOK / 128), 256, SMEM_NN>>>(
            hsh, hsl, wh, wl, b1 + (size_t)l * FFD, nullptr, ah, al, TOK, FFD, DM);
        // ffn out = hidden @ W2 + b2
        split(W2 + (size_t)l * FFD * DM, wh, wl, (size_t)FFD * DM);
        k_mgemm<0, false, false><<<dim3(DM / 128, TOK / 128), 256, SMEM_NN>>>(
            ah, al, wh, wl, b2 + (size_t)l * DM, tmp, nullptr, nullptr, TOK, DM, FFD);
        // core = LN(h + ffn) (+ split for next QKV / logits)
        k_lnres<<<TOK, 256>>>(h, tmp, ln2_g + l * DM, ln2_b + l * DM, core, ch, cl);
    }

    // logits = core @ emb^T + dec_b  (champion raster: x=N, y=M)
    k_mgemm<0, true, false><<<dim3(VC / 128, TOK / 128), 256, SMEM_NT>>>(
        ch, cl, eh, el, dec_b, out, nullptr, nullptr, TOK, VC, DM);
}

// round 17
// speedup vs baseline: 1.0285x; 1.0285x over previous
#include <cuda_runtime.h>
#include <cuda_bf16.h>
#include <math.h>
#include <stdint.h>

// Model dims
#define QL 512
#define BS 8
#define VC 32000
#define DM 1024
#define NH 16
#define DHD 64
#define FFD 4096
#define NL 4
#define RL 513
#define TOK 4096
#define BH 128
#define ATT_SCALE 0.125f
#define MROWS (TOK + RL)          // merged QKV GEMM rows (core + r)

// ---------------------------------------------------------------------------
// Scratch
// ---------------------------------------------------------------------------
__device__ float g_core[TOK * DM];
__device__ float g_big[TOK * FFD];          // QKV+rqkv output (rows 0..4608 x 3072) / FFN hidden
__device__ float g_tmp[TOK * DM];
__device__ float g_h[TOK * DM];
__device__ float g_qr[(size_t)BH * QL * RL];
// bf16 split buffers
__device__ __nv_bfloat16 g_ah[TOK * FFD];        // FFN1 output split hi
__device__ __nv_bfloat16 g_al[TOK * FFD];        // FFN1 output split lo
__device__ __nv_bfloat16 g_wh[DM * FFD];         // weight split
__device__ __nv_bfloat16 g_wl[DM * FFD];
__device__ __nv_bfloat16 g_eh[(size_t)VC * DM];  // embedding split
__device__ __nv_bfloat16 g_el[(size_t)VC * DM];
__device__ __nv_bfloat16 g_ch[(size_t)MROWS * DM];  // core split + r split tail
__device__ __nv_bfloat16 g_cl[(size_t)MROWS * DM];
__device__ __nv_bfloat16 g_vh[TOK * DM];         // attn-vec split (feeds Wo)
__device__ __nv_bfloat16 g_vl[TOK * DM];
__device__ __nv_bfloat16 g_hsh[TOK * DM];        // h split (feeds FFN1)
__device__ __nv_bfloat16 g_hsl[TOK * DM];

static __device__ __forceinline__ uint32_t s2u(const void* p) {
    return (uint32_t)__cvta_generic_to_shared(p);
}

#define LDSM4(R, addr)                                                           \
    asm volatile("ldmatrix.sync.aligned.m8n8.x4.shared.b16 {%0,%1,%2,%3}, [%4];" \
                 : "=r"(R[0]), "=r"(R[1]), "=r"(R[2]), "=r"(R[3]) : "r"(addr));
#define LDSM4T(R, addr)                                                                \
    asm volatile("ldmatrix.sync.aligned.m8n8.x4.trans.shared.b16 {%0,%1,%2,%3}, [%4];" \
                 : "=r"(R[0]), "=r"(R[1]), "=r"(R[2]), "=r"(R[3]) : "r"(addr));
#define MMA_BF16(ac, A, b0, b1)                                                  \
    asm volatile("mma.sync.aligned.m16n8k16.row.col.f32.bf16.bf16.f32 "          \
                 "{%0,%1,%2,%3}, {%4,%5,%6,%7}, {%8,%9}, {%0,%1,%2,%3};"         \
                 : "+f"(ac[0]), "+f"(ac[1]), "+f"(ac[2]), "+f"(ac[3])            \
                 : "r"(A[0]), "r"(A[1]), "r"(A[2]), "r"(A[3]), "r"(b0), "r"(b1));

static __device__ __forceinline__ void cp16(__nv_bfloat16* dst,
                                            const __nv_bfloat16* src, bool pred) {
    uint32_t d = s2u(dst);
    int n = pred ? 16 : 0;
    asm volatile("cp.async.cg.shared.global [%0], [%1], 16, %2;" ::"r"(d), "l"(src), "r"(n));
}

static __device__ __forceinline__ void split1(float v, __nv_bfloat16& hi, __nv_bfloat16& lo) {
    hi = __float2bfloat16(v);
    lo = __float2bfloat16(v - __bfloat162float(hi));
}

static __device__ __forceinline__ void split_store4(float x0, float x1, float x2, float x3,
                                                    __nv_bfloat16* H, __nv_bfloat16* L) {
    __nv_bfloat16 h0, h1, h2, h3, l0, l1, l2, l3;
    split1(x0, h0, l0); split1(x1, h1, l1);
    split1(x2, h2, l2); split1(x3, h3, l3);
    *(__nv_bfloat162*)(H)     = __nv_bfloat162(h0, h1);
    *(__nv_bfloat162*)(H + 2) = __nv_bfloat162(h2, h3);
    *(__nv_bfloat162*)(L)     = __nv_bfloat162(l0, l1);
    *(__nv_bfloat162*)(L + 2) = __nv_bfloat162(l2, l3);
}

// ---------------------------------------------------------------------------
// Split fp32 -> (hi, lo) bf16
// ---------------------------------------------------------------------------
__global__ void k_split(const float* __restrict__ x, __nv_bfloat16* __restrict__ h,
                        __nv_bfloat16* __restrict__ l, int n) {
    int i = (blockIdx.x * 256 + threadIdx.x) * 4;
    if (i >= n) return;
    float4 v = *(const float4*)(x + i);
    split_store4(v.x, v.y, v.z, v.w, h + i, l + i);
}

// ---------------------------------------------------------------------------
// Split-bf16 tensor-core GEMM, 2-stage cp.async pipeline (champion loop).
// ---------------------------------------------------------------------------
template <int ACT, bool TB, bool SPLIT_OUT>
__global__ __launch_bounds__(256, 2)
void k_mgemm(const __nv_bfloat16* __restrict__ Ah, const __nv_bfloat16* __restrict__ Al,
             const __nv_bfloat16* __restrict__ Bh, const __nv_bfloat16* __restrict__ Bl,
             const float* __restrict__ bias, float* __restrict__ C,
             __nv_bfloat16* __restrict__ Oh, __nv_bfloat16* __restrict__ Ol,
             int M, int N, int K) {
    constexpr int BSTR = TB ? 40 : 136;
    constexpr int ASTG = 128 * 40;
    constexpr int BSTG = TB ? 128 * 40 : 32 * 136;
    constexpr int STG = 2 * ASTG + 2 * BSTG;
    extern __shared__ __nv_bfloat16 smem[];

    int tid = threadIdx.x;
    int m0 = blockIdx.y << 7, n0 = blockIdx.x << 7;
    int lane = tid & 31, warp = tid >> 5;
    int wm = warp >> 1, wn = warp & 1;

    float acc[2][8][4];
#pragma unroll
    for (int a = 0; a < 2; a++)
#pragma unroll
        for (int b = 0; b < 8; b++)
#pragma unroll
            for (int c = 0; c < 4; c++) acc[a][b][c] = 0.f;

    auto load_stage = [&](int k0, int s) {
        __nv_bfloat16* sAh = smem + s * STG;
        __nv_bfloat16* sAl = sAh + ASTG;
        __nv_bfloat16* sBh = sAl + ASTG;
        __nv_bfloat16* sBl = sBh + BSTG;
#pragma unroll
        for (int u = 0; u < 2; u++) {
            int p = tid + u * 256;
            int row = p >> 2, kq = (p & 3) << 3;
            bool ok = (m0 + row) < M;
            size_t off = (size_t)(m0 + row) * K + k0 + kq;
            cp16(&sAh[row * 40 + kq], Ah + off, ok);
            cp16(&sAl[row * 40 + kq], Al + off, ok);
        }
#pragma unroll
        for (int u = 0; u < 2; u++) {
            int p = tid + u * 256;
            if (TB) {
                int row = p >> 2, kq = (p & 3) << 3;
                size_t off = (size_t)(n0 + row) * K + k0 + kq;
                cp16(&sBh[row * 40 + kq], Bh + off, true);
                cp16(&sBl[row * 40 + kq], Bl + off, true);
            } else {
                int row = p >> 4, nq = (p & 15) << 3;
                size_t off = (size_t)(k0 + row) * N + n0 + nq;
                cp16(&sBh[row * 136 + nq], Bh + off, true);
                cp16(&sBl[row * 136 + nq], Bl + off, true);
            }
        }
        asm volatile("cp.async.commit_group;");
    };

    int KT = K >> 5;
    load_stage(0, 0);

    for (int kt = 0; kt < KT; kt++) {
        if (kt + 1 < KT) load_stage((kt + 1) << 5, (kt + 1) & 1);
        else asm volatile("cp.async.commit_group;");
        asm volatile("cp.async.wait_group 1;");
        __syncthreads();

        const __nv_bfloat16* sAh = smem + (kt & 1) * STG;
        const __nv_bfloat16* sAl = sAh + ASTG;
        const __nv_bfloat16* sBh = sAl + ASTG;
        const __nv_bfloat16* sBl = sBh + BSTG;

#pragma unroll
        for (int ks = 0; ks < 32; ks += 16) {
            uint32_t ah[2][4], al[2][4];
#pragma unroll
            for (int mt = 0; mt < 2; mt++) {
                int rb = wm * 32 + mt * 16 + (lane & 15);
                int kc = ks + ((lane >> 4) << 3);
                LDSM4(ah[mt], s2u(&sAh[rb * 40 + kc]));
                LDSM4(al[mt], s2u(&sAl[rb * 40 + kc]));
            }
#pragma unroll
            for (int np = 0; np < 4; np++) {
                int nb = wn * 64 + np * 16;
                uint32_t bh[4], bl[4];
                int g = lane >> 3, l8 = lane & 7;
                if (TB) {
                    int nr = nb + ((g >> 1) << 3) + l8;
                    int kc = ks + ((g & 1) << 3);
                    LDSM4(bh, s2u(&sBh[nr * BSTR + kc]));
                    LDSM4(bl, s2u(&sBl[nr * BSTR + kc]));
                } else {
                    int kr = ks + ((g & 1) << 3) + l8;
                    int nc = nb + ((g >> 1) << 3);
                    LDSM4T(bh, s2u(&sBh[kr * BSTR + nc]));
                    LDSM4T(bl, s2u(&sBl[kr * BSTR + nc]));
                }
#pragma unroll
                for (int mt = 0; mt < 2; mt++) {
#pragma unroll
                    for (int j = 0; j < 2; j++) {
                        float* ac = acc[mt][np * 2 + j];
                        MMA_BF16(ac, ah[mt], bh[2 * j], bh[2 * j + 1]);
                        MMA_BF16(ac, ah[mt], bl[2 * j], bl[2 * j + 1]);
                        MMA_BF16(ac, al[mt], bh[2 * j], bh[2 * j + 1]);
                    }
                }
            }
        }
        __syncthreads();
    }

#pragma unroll
    for (int mt = 0; mt < 2; mt++) {
#pragma unroll
        for (int np = 0; np < 4; np++) {
#pragma unroll
            for (int j = 0; j < 2; j++) {
                int nt = np * 2 + j;
                int col = n0 + wn * 64 + np * 16 + j * 8 + (lane & 3) * 2;
                int rb = m0 + wm * 32 + mt * 16 + (lane >> 2);
#pragma unroll
                for (int hh = 0; hh < 2; hh++) {
                    int r = rb + hh * 8;
                    if (r >= M) continue;
                    float v0 = acc[mt][nt][hh * 2];
                    float v1 = acc[mt][nt][hh * 2 + 1];
                    if (bias) { v0 += bias[col]; v1 += bias[col + 1]; }
                    if (ACT == 1) {
                        v0 = 0.5f * v0 * (1.f + erff(v0 * 0.70710678118654752f));
                        v1 = 0.5f * v1 * (1.f + erff(v1 * 0.70710678118654752f));
                    }
                    if (SPLIT_OUT) {
                        __nv_bfloat16 h0, h1, l0, l1;
                        split1(v0, h0, l0);
                        split1(v1, h1, l1);
                        *(__nv_bfloat162*)(Oh + (size_t)r * N + col) = __nv_bfloat162(h0, h1);
                        *(__nv_bfloat162*)(Ol + (size_t)r * N + col) = __nv_bfloat162(l0, l1);
                    } else {
                        *(float2*)(C + (size_t)r * N + col) = make_float2(v0, v1);
                    }
                }
            }
        }
    }
}

// ---------------------------------------------------------------------------
// Embedding lookup * sqrt(D) + fused core split (rows 0..TOK-1 of ch/cl)
// ---------------------------------------------------------------------------
__global__ void k_embed(const int* __restrict__ src, const float* __restrict__ emb) {
    int t = blockIdx.x;
    int tok = src[t];
    const float4* e = (const float4*)(emb + (size_t)tok * DM);
    size_t base = (size_t)t * DM;
    for (int d = threadIdx.x; d < DM / 4; d += blockDim.x) {
        float4 v = e[d];
        v.x *= 32.f; v.y *= 32.f; v.z *= 32.f; v.w *= 32.f;
        *(float4*)(g_core + base + d * 4) = v;
        split_store4(v.x, v.y, v.z, v.w, g_ch + base + d * 4, g_cl + base + d * 4);
    }
}

// ---------------------------------------------------------------------------
// Positional embedding, split directly into ch/cl tail rows (TOK..TOK+RL-1)
// ---------------------------------------------------------------------------
__global__ void k_posemb() {
    int p = blockIdx.x;
    double pos = (double)(QL - p);
    size_t tail = (size_t)(TOK + p) * DM;
    for (int d = threadIdx.x; d < DM; d += blockDim.x) {
        int j = d & 511;
        double inv = exp(-((double)(2 * j) / (double)DM) * log(10000.0));
        double a = pos * inv;
        float v = (d < 512) ? (float)sin(a) : (float)cos(a);
        __nv_bfloat16 hi, lo;
        split1(v, hi, lo);
        g_ch[tail + d] = hi;
        g_cl[tail + d] = lo;
    }
}

// ---------------------------------------------------------------------------
// fp32 64x64 NT tile MMA (proven attention compute primitive)
// ---------------------------------------------------------------------------
__device__ __forceinline__ void mma_nt64(const float (*X)[68], const float (*Y)[68],
                                         int ty, int tx, float acc[4][4]) {
#pragma unroll
    for (int d4 = 0; d4 < 16; d4++) {
        float4 xv[4], yv[4];
#pragma unroll
        for (int ii = 0; ii < 4; ii++) xv[ii] = *(const float4*)&X[ty * 4 + ii][d4 * 4];
#pragma unroll
        for (int jj = 0; jj < 4; jj++) yv[jj] = *(const float4*)&Y[tx * 4 + jj][d4 * 4];
#pragma unroll
        for (int ii = 0; ii < 4; ii++)
#pragma unroll
            for (int jj = 0; jj < 4; jj++)
                acc[ii][jj] += xv[ii].x * yv[jj].x + xv[ii].y * yv[jj].y +
                               xv[ii].z * yv[jj].z + xv[ii].w * yv[jj].w;
    }
}

// rqkv now lives in g_big rows TOK..TOK+RL-1 (stride 3*DM)
#define RQKV_ROW(jr) (g_big + (size_t)(TOK + (jr)) * (3 * DM))

// ---------------------------------------------------------------------------
// k_qr: qr[bn,i,jr] = q_bias . rk
// ---------------------------------------------------------------------------
__global__ __launch_bounds__(256) void k_qr() {
    int bn = blockIdx.z, b = bn >> 4, n = bn & 15;
    int i0 = blockIdx.y << 6, jr0 = blockIdx.x << 6;
    if (jr0 + i0 + 126 < QL) return;
    __shared__ float Qs[64][68], Rs[64][68];
    int tid = threadIdx.x;
    const float* rql = RQKV_ROW(QL) + n * DHD;
#pragma unroll
    for (int u = 0; u < 16; u++) {
        int idx = tid + u * 256;
        int rr = idx >> 6, d = idx & 63;
        Qs[rr][d] = g_big[((size_t)(i0 + rr) * BS + b) * (3 * DM) + n * DHD + d] + rql[d];
        int jr = jr0 + rr;
        Rs[rr][d] = (jr < RL) ? RQKV_ROW(jr)[DM + n * DHD + d] : 0.f;
    }
    __syncthreads();
    int ty = tid >> 4, tx = tid & 15;
    float acc[4][4] = {};
    mma_nt64(Qs, Rs, ty, tx, acc);
    float* out = g_qr + (size_t)bn * QL * RL;
#pragma unroll
    for (int ii = 0; ii < 4; ii++) {
        int i = i0 + ty * 4 + ii;
#pragma unroll
        for (int jj = 0; jj < 4; jj++) {
            int jr = jr0 + tx * 4 + jj;
            if (jr < RL) out[(size_t)i * RL + jr] = acc[ii][jj];
        }
    }
}

// ---------------------------------------------------------------------------
// Fused flash attention (champion-identical except rql source)
// ---------------------------------------------------------------------------
__global__ __launch_bounds__(256) void k_flash() {
    int bn = blockIdx.y, b = bn >> 4, n = bn & 15;
    int it = blockIdx.x;
    int i0 = it << 6;
    extern __shared__ float fsm[];
    float (*Qs)[68] = (float(*)[68])fsm;
    float (*Ks)[68] = (float(*)[68])(fsm + 64 * 68);
    float (*Vs)[68] = (float(*)[68])(fsm + 2 * 64 * 68);
    float (*Ps)[68] = (float(*)[68])(fsm + 3 * 64 * 68);
    int tid = threadIdx.x, ty = tid >> 4, tx = tid & 15;

    const float* rql = RQKV_ROW(QL) + n * DHD;
#pragma unroll
    for (int u = 0; u < 16; u++) {
        int idx = tid + u * 256;
        int rr = idx >> 6, d = idx & 63;
        Qs[rr][d] = g_big[((size_t)(i0 + rr) * BS + b) * (3 * DM) + n * DHD + d] + rql[d];
    }

    float o[4][4];
    float m[4], l[4];
#pragma unroll
    for (int ii = 0; ii < 4; ii++) {
        m[ii] = -INFINITY;
        l[ii] = 0.f;
#pragma unroll
        for (int jj = 0; jj < 4; jj++) o[ii][jj] = 0.f;
    }

    const float* qrb = g_qr + (size_t)bn * QL * RL;

    for (int jt = 0; jt <= it; jt++) {
        int j0 = jt << 6;
        __syncthreads();
#pragma unroll
        for (int u = 0; u < 16; u++) {
            int idx = tid + u * 256;
            int rr = idx >> 6, d = idx & 63;
            Ks[rr][d] = g_big[((size_t)(j0 + rr) * BS + b) * (3 * DM) + DM + n * DHD + d];
            Vs[rr][d] = g_big[((size_t)(j0 + rr) * BS + b) * (3 * DM) + 2 * DM + n * DHD + d];
        }
        __syncthreads();

        float acc[4][4] = {};
        mma_nt64(Qs, Ks, ty, tx, acc);

#pragma unroll
        for (int ii = 0; ii < 4; ii++) {
            int i = i0 + ty * 4 + ii;
            float s[4];
#pragma unroll
            for (int jj = 0; jj < 4; jj++) {
                int j = j0 + tx * 4 + jj;
                s[jj] = (j > i) ? -INFINITY
                                : (acc[ii][jj] + qrb[(size_t)i * RL + (QL + j - i)]) * ATT_SCALE;
            }
            float mx = fmaxf(fmaxf(s[0], s[1]), fmaxf(s[2], s[3]));
#pragma unroll
            for (int off = 8; off >= 1; off >>= 1)
                mx = fmaxf(mx, __shfl_xor_sync(0xffffffffu, mx, off));
            float newm = fmaxf(m[ii], mx);
            float corr = expf(m[ii] - newm);
            float p[4];
            float ps = 0.f;
#pragma unroll
            for (int jj = 0; jj < 4; jj++) {
                p[jj] = expf(s[jj] - newm);
                ps += p[jj];
            }
#pragma unroll
            for (int off = 8; off >= 1; off >>= 1)
                ps += __shfl_xor_sync(0xffffffffu, ps, off);
            l[ii] = l[ii] * corr + ps;
            m[ii] = newm;
#pragma unroll
            for (int jj = 0; jj < 4; jj++) o[ii][jj] *= corr;
            *(float4*)&Ps[ty * 4 + ii][tx * 4] = make_float4(p[0], p[1], p[2], p[3]);
        }
        __syncthreads();

#pragma unroll
        for (int k4 = 0; k4 < 16; k4++) {
            float4 pr[4];
#pragma unroll
            for (int ii = 0; ii < 4; ii++) pr[ii] = *(const float4*)&Ps[ty * 4 + ii][k4 * 4];
#pragma unroll
            for (int kk = 0; kk < 4; kk++) {
                float4 vv = *(const float4*)&Vs[k4 * 4 + kk][tx * 4];
#pragma unroll
                for (int ii = 0; ii < 4; ii++) {
                    float pv = ((const float*)&pr[ii])[kk];
                    o[ii][0] += pv * vv.x;
                    o[ii][1] += pv * vv.y;
                    o[ii][2] += pv * vv.z;
                    o[ii][3] += pv * vv.w;
                }
            }
        }
    }

#pragma unroll
    for (int ii = 0; ii < 4; ii++) {
        float invl = 1.f / l[ii];
        int i = i0 + ty * 4 + ii;
        size_t off = ((size_t)i * BS + b) * DM + n * DHD + tx * 4;
        split_store4(o[ii][0] * invl, o[ii][1] * invl, o[ii][2] * invl, o[ii][3] * invl,
                     g_vh + off, g_vl + off);
    }
}

// ---------------------------------------------------------------------------
// O = LayerNorm(A + B) * gamma + beta; optional fused split outputs
// ---------------------------------------------------------------------------
__global__ __launch_bounds__(256) void k_lnres(const float* __restrict__ A,
                                               const float* __restrict__ Bi,
                                               const float* __restrict__ G,
                                               const float* __restrict__ Be,
                                               float* __restrict__ O,
                                               __nv_bfloat16* __restrict__ Oh,
                                               __nv_bfloat16* __restrict__ Ol) {
    int row = blockIdx.x, tid = threadIdx.x;
    size_t base = (size_t)row * DM + tid * 4;
    float4 va = *(const float4*)(A + base);
    float4 vb = *(const float4*)(Bi + base);
    float x[4] = {va.x + vb.x, va.y + vb.y, va.z + vb.z, va.w + vb.w};
    float s = x[0] + x[1] + x[2] + x[3];
    float s2 = x[0] * x[0] + x[1] * x[1] + x[2] * x[2] + x[3] * x[3];
    __shared__ float rs[256], rs2[256];
    rs[tid] = s;
    rs2[tid] = s2;
    __syncthreads();
    for (int st = 128; st > 0; st >>= 1) {
        if (tid < st) { rs[tid] += rs[tid + st]; rs2[tid] += rs2[tid + st]; }
        __syncthreads();
    }
    float mean = rs[0] * (1.f / (float)DM);
    float var = rs2[0] * (1.f / (float)DM) - mean * mean;
    float inv = rsqrtf(var + 1e-5f);
    float4 g4 = *(const float4*)(G + tid * 4);
    float4 b4 = *(const float4*)(Be + tid * 4);
    float y[4];
    y[0] = (x[0] - mean) * inv * g4.x + b4.x;
    y[1] = (x[1] - mean) * inv * g4.y + b4.y;
    y[2] = (x[2] - mean) * inv * g4.z + b4.z;
    y[3] = (x[3] - mean) * inv * g4.w + b4.w;
    *(float4*)(O + base) = make_float4(y[0], y[1], y[2], y[3]);
    if (Oh) split_store4(y[0], y[1], y[2], y[3], Oh + base, Ol + base);
}

// ---------------------------------------------------------------------------
// Fused double-LN: src2 = LN(core+att); h = LN(core+src2)
// ---------------------------------------------------------------------------
__global__ __launch_bounds__(256) void k_lnres2(const float* __restrict__ core,
                                                const float* __restrict__ att,
                                                const float* __restrict__ G0,
                                                const float* __restrict__ B0,
                                                const float* __restrict__ G1,
                                                const float* __restrict__ B1,
                                                float* __restrict__ H,
                                                __nv_bfloat16* __restrict__ Hh,
                                                __nv_bfloat16* __restrict__ Hl) {
    int row = blockIdx.x, tid = threadIdx.x;
    size_t base = (size_t)row * DM + tid * 4;
    float4 vc = *(const float4*)(core + base);
    float4 va = *(const float4*)(att + base);
    float c[4] = {vc.x, vc.y, vc.z, vc.w};
    float x[4] = {vc.x + va.x, vc.y + va.y, vc.z + va.z, vc.w + va.w};
    __shared__ float rs[256], rs2[256];
    float s = x[0] + x[1] + x[2] + x[3];
    float s2 = x[0] * x[0] + x[1] * x[1] + x[2] * x[2] + x[3] * x[3];
    rs[tid] = s; rs2[tid] = s2;
    __syncthreads();
    for (int st = 128; st > 0; st >>= 1) {
        if (tid < st) { rs[tid] += rs[tid + st]; rs2[tid] += rs2[tid + st]; }
        __syncthreads();
    }
    float mean = rs[0] * (1.f / (float)DM);
    float var = rs2[0] * (1.f / (float)DM) - mean * mean;
    float inv = rsqrtf(var + 1e-5f);
    float4 g0 = *(const float4*)(G0 + tid * 4);
    float4 b0 = *(const float4*)(B0 + tid * 4);
    float y[4];   // core + src2
    y[0] = c[0] + (x[0] - mean) * inv * g0.x + b0.x;
    y[1] = c[1] + (x[1] - mean) * inv * g0.y + b0.y;
    y[2] = c[2] + (x[2] - mean) * inv * g0.z + b0.z;
    y[3] = c[3] + (x[3] - mean) * inv * g0.w + b0.w;
    __syncthreads();
    s = y[0] + y[1] + y[2] + y[3];
    s2 = y[0] * y[0] + y[1] * y[1] + y[2] * y[2] + y[3] * y[3];
    rs[tid] = s; rs2[tid] = s2;
    __syncthreads();
    for (int st = 128; st > 0; st >>= 1) {
        if (tid < st) { rs[tid] += rs[tid + st]; rs2[tid] += rs2[tid + st]; }
        __syncthreads();
    }
    mean = rs[0] * (1.f / (float)DM);
    var = rs2[0] * (1.f / (float)DM) - mean * mean;
    inv = rsqrtf(var + 1e-5f);
    float4 g1 = *(const float4*)(G1 + tid * 4);
    float4 b1 = *(const float4*)(B1 + tid * 4);
    float h[4];
    h[0] = (y[0] - mean) * inv * g1.x + b1.x;
    h[1] = (y[1] - mean) * inv * g1.y + b1.y;
    h[2] = (y[2] - mean) * inv * g1.z + b1.z;
    h[3] = (y[3] - mean) * inv * g1.w + b1.w;
    *(float4*)(H + base) = make_float4(h[0], h[1], h[2], h[3]);
    split_store4(h[0], h[1], h[2], h[3], Hh + base, Hl + base);
}

// ---------------------------------------------------------------------------
// Launch sequence. rqkv merged into the QKV GEMM (A-row concatenation):
// rows 0..TOK-1 = core split, rows TOK..TOK+RL-1 = r split (constant tail).
// ---------------------------------------------------------------------------
extern "C" void kernel_launch(void* const* d_in, const int* in_sizes, int n_in,
                              void* d_out, int out_size) {
    const int*   src   = (const int*)d_in[0];
    const float* emb   = (const float*)d_in[1];
    const float* dec_b = (const float*)d_in[2];
    const float* Wqkv  = (const float*)d_in[3];
    const float* Wo    = (const float*)d_in[4];
    const float* ln0_g = (const float*)d_in[5];
    const float* ln0_b = (const float*)d_in[6];
    const float* W1    = (const float*)d_in[7];
    const float* b1    = (const float*)d_in[8];
    const float* W2    = (const float*)d_in[9];
    const float* b2    = (const float*)d_in[10];
    const float* ln1_g = (const float*)d_in[11];
    const float* ln1_b = (const float*)d_in[12];
    const float* ln2_g = (const float*)d_in[13];
    const float* ln2_b = (const float*)d_in[14];
    float* out = (float*)d_out;

    float *core, *big, *tmp, *h;
    cudaGetSymbolAddress((void**)&core, g_core);
    cudaGetSymbolAddress((void**)&big,  g_big);
    cudaGetSymbolAddress((void**)&tmp,  g_tmp);
    cudaGetSymbolAddress((void**)&h,    g_h);
    __nv_bfloat16 *ah, *al, *wh, *wl, *eh, *el, *ch, *cl, *vh, *vl, *hsh, *hsl;
    cudaGetSymbolAddress((void**)&ah,  g_ah);
    cudaGetSymbolAddress((void**)&al,  g_al);
    cudaGetSymbolAddress((void**)&wh,  g_wh);
    cudaGetSymbolAddress((void**)&wl,  g_wl);
    cudaGetSymbolAddress((void**)&eh,  g_eh);
    cudaGetSymbolAddress((void**)&el,  g_el);
    cudaGetSymbolAddress((void**)&ch,  g_ch);
    cudaGetSymbolAddress((void**)&cl,  g_cl);
    cudaGetSymbolAddress((void**)&vh,  g_vh);
    cudaGetSymbolAddress((void**)&vl,  g_vl);
    cudaGetSymbolAddress((void**)&hsh, g_hsh);
    cudaGetSymbolAddress((void**)&hsl, g_hsl);

    const int SMEM_NN = 75776, SMEM_NT = 81920;
    const int SMEM_FLASH = 4 * 64 * 68 * 4;   // 69632
    cudaFuncSetAttribute(k_mgemm<0, false, false>,
                         cudaFuncAttributeMaxDynamicSharedMemorySize, SMEM_NN);
    cudaFuncSetAttribute(k_mgemm<1, false, true>,
                         cudaFuncAttributeMaxDynamicSharedMemorySize, SMEM_NN);
    cudaFuncSetAttribute(k_mgemm<0, true, false>,
                         cudaFuncAttributeMaxDynamicSharedMemorySize, SMEM_NT);
    cudaFuncSetAttribute(k_flash,
                         cudaFuncAttributeMaxDynamicSharedMemorySize, SMEM_FLASH);

    auto split = [](const float* x, __nv_bfloat16* hh, __nv_bfloat16* ll, size_t n) {
        k_split<<<(unsigned)((n + 1023) / 1024), 256>>>(x, hh, ll, (int)n);
    };

    const unsigned MT = (MROWS + 127) / 128;   // 37 m-tiles for merged QKV GEMM

    // Prologue — merged QKV GEMM of layer 0 at launch #4 (ncu capture slot).
    k_embed<<<TOK, 256>>>(src, emb);                 // #1: core fp32 + ch/cl rows 0..TOK-1
    k_posemb<<<RL, 256>>>();                         // #2: ch/cl tail rows (r split)
    split(Wqkv, wh, wl, (size_t)DM * 3 * DM);        // #3: layer-0 weight split
    k_mgemm<0, false, false><<<dim3(3 * DM / 128, MT), 256, SMEM_NN>>>(
        ch, cl, wh, wl, nullptr, big, nullptr, nullptr, MROWS, 3 * DM, DM);  // #4
    split(emb, eh, el, (size_t)VC * DM);

    for (int l = 0; l < NL; l++) {
        const float* Wq = Wqkv + (size_t)l * DM * 3 * DM;
        if (l > 0) {
            split(Wq, wh, wl, (size_t)DM * 3 * DM);
            // merged [core; r] @ Wqkv[l]
            k_mgemm<0, false, false><<<dim3(3 * DM / 128, MT), 256, SMEM_NN>>>(
                ch, cl, wh, wl, nullptr, big, nullptr, nullptr, MROWS, 3 * DM, DM);
        }
        // attention: qr, then fused score+softmax+PV
        k_qr<<<dim3(9, 8, BH), 256>>>();
        k_flash<<<dim3(8, BH), 256, SMEM_FLASH>>>();   // -> (vh, vl)
        // attn_out = vec @ Wo[l]
        split(Wo + (size_t)l * DM * DM, wh, wl, (size_t)DM * DM);
        k_mgemm<0, false, false><<<dim3(DM / 128, TOK / 128), 256, SMEM_NN>>>(
            vh, vl, wh, wl, nullptr, tmp, nullptr, nullptr, TOK, DM, DM);
        // fused: src2 = LN(core+att); h = LN(core+src2) (+ split for FFN1)
        k_lnres2<<<TOK, 256>>>(core, tmp, ln0_g + l * DM, ln0_b + l * DM,
                               ln1_g + l * DM, ln1_b + l * DM, h, hsh, hsl);
        // ffn hidden = gelu(h @ W1 + b1) -> split bf16 directly
        split(W1 + (size_t)l * DM * FFD, wh, wl, (size_t)DM * FFD);
        k_mgemm<1, false, true><<<dim3(FFD / 128, TOK / 128), 256, SMEM_NN>>>(
            hsh, hsl, wh, wl, b1 + (size_t)l * FFD, nullptr, ah, al, TOK, FFD, DM);
        // ffn out = hidden @ W2 + b2
        split(W2 + (size_t)l * FFD * DM, wh, wl, (size_t)FFD * DM);
        k_mgemm<0, false, false><<<dim3(DM / 128, TOK / 128), 256, SMEM_NN>>>(
            ah, al, wh, wl, b2 + (size_t)l * DM, tmp, nullptr, nullptr, TOK, DM, FFD);
        // core = LN(h + ffn) (+ split rows 0..TOK-1 of ch/cl; r tail untouched)
        k_lnres<<<TOK, 256>>>(h, tmp, ln2_g + l * DM, ln2_b + l * DM, core, ch, cl);
    }

    // logits = core @ emb^T + dec_b  (champion raster: x=N, y=M; A rows 0..TOK-1)
    k_mgemm<0, true, false><<<dim3(VC / 128, TOK / 128), 256, SMEM_NT>>>(
        ch, cl, eh, el, dec_b, out, nullptr, nullptr, TOK, VC, DM);
}